// round 14
// baseline (speedup 1.0000x reference)
#include <cuda_runtime.h>

// ---------------------------------------------------------------------------
// RNN_32109175505717: 3-layer tanh RNN (B=4096, T=128, HID=64, F=14) + FC head
// R14 = R13 (256 thr, layer-skew pipeline, j-pair accumulators, ksplit 4,
// 2 barriers/step) with the three independent jobs INTERLEAVED in one mv loop:
// 3 independent load->fma chains per iteration to cover LDS latency
// (ncu: 34% of step time was exposed latency, no pipe saturated).
// Traffic and instruction counts identical to R13.
// ---------------------------------------------------------------------------

#define HID      64
#define F_IN     14
#define T_STEPS  128
#define ELEMS    32
#define NTHREADS 256
#define NBLOCKS  128
#define NSUPER   (T_STEPS + 2)

typedef unsigned long long ull;

// ---- float-region (weights [k][j], 68-float rows) -------------------------
#define WROW   68
#define WF_A   0                       // 80 rows: [Wih0(14); zero(2); Whh0(64)]
#define WF_B   (WF_A + 80*WROW)        // 128 rows: [Wih1; Whh1]
#define WF_C   (WF_B + 128*WROW)       // 128 rows: [Wih2; Whh2]
#define WF_END (WF_C + 128*WROW)       // 22848 floats
// ---- ull-region -----------------------------------------------------------
#define U_XS   (WF_END/2)
#define U_H0   (U_XS + 16*18)
#define U_H1   (U_H0 + 64*18)
#define U_H2   (U_H1 + 64*18)
#define U_RED  (U_H2 + 64*18)          // 12 quadrants x [32 jp][36 ull]
#define RED_Q  1152
#define RED_ROW 36
#define U_END  (U_RED + 12*RED_Q)      // 231936 B
#define U_FCRED U_RED
#define SMEM_BYTES (U_END * 8)

// ---- f32x2 helpers --------------------------------------------------------
__device__ __forceinline__ ull pack2(float lo, float hi) {
    ull r; asm("mov.b64 %0, {%1, %2};" : "=l"(r) : "f"(lo), "f"(hi)); return r;
}
__device__ __forceinline__ void unpack2(ull v, float& lo, float& hi) {
    asm("mov.b64 {%0, %1}, %2;" : "=f"(lo), "=f"(hi) : "l"(v));
}
__device__ __forceinline__ ull fma2(ull a, ull b, ull c) {
    ull d; asm("fma.rn.f32x2 %0, %1, %2, %3;" : "=l"(d) : "l"(a), "l"(b), "l"(c));
    return d;
}
__device__ __forceinline__ ull add2(ull a, ull b) {
    ull d; asm("add.rn.f32x2 %0, %1, %2;" : "=l"(d) : "l"(a), "l"(b));
    return d;
}
__device__ __forceinline__ float fast_tanh(float x) {
    x = fminf(fmaxf(x, -12.0f), 12.0f);
    float e = __expf(x + x);
    return __fdividef(e - 1.0f, e + 1.0f);
}
__device__ __forceinline__ ull tanh2(ull v) {
    float a, b; unpack2(v, a, b);
    return pack2(fast_tanh(a), fast_tanh(b));
}

// ---- one k-row: 4 j-pairs x 4 e ------------------------------------------
__device__ __forceinline__ void mv_one(const float* __restrict__ wf,
                                       const float* __restrict__ hb,
                                       int k, int w8, int u4, ull a[4][4])
{
    float4 hv = *reinterpret_cast<const float4*>(hb + k * 36 + u4);
    const float* wr = wf + k * WROW + w8;
    ulonglong2 w01 = *reinterpret_cast<const ulonglong2*>(wr);
    ulonglong2 w23 = *reinterpret_cast<const ulonglong2*>(wr + 4);
    ull ph;
    ph = pack2(hv.x, hv.x);
    a[0][0]=fma2(w01.x,ph,a[0][0]); a[1][0]=fma2(w01.y,ph,a[1][0]);
    a[2][0]=fma2(w23.x,ph,a[2][0]); a[3][0]=fma2(w23.y,ph,a[3][0]);
    ph = pack2(hv.y, hv.y);
    a[0][1]=fma2(w01.x,ph,a[0][1]); a[1][1]=fma2(w01.y,ph,a[1][1]);
    a[2][1]=fma2(w23.x,ph,a[2][1]); a[3][1]=fma2(w23.y,ph,a[3][1]);
    ph = pack2(hv.z, hv.z);
    a[0][2]=fma2(w01.x,ph,a[0][2]); a[1][2]=fma2(w01.y,ph,a[1][2]);
    a[2][2]=fma2(w23.x,ph,a[2][2]); a[3][2]=fma2(w23.y,ph,a[3][2]);
    ph = pack2(hv.w, hv.w);
    a[0][3]=fma2(w01.x,ph,a[0][3]); a[1][3]=fma2(w01.y,ph,a[1][3]);
    a[2][3]=fma2(w23.x,ph,a[2][3]); a[3][3]=fma2(w23.y,ph,a[3][3]);
}

// red partial store: 4 j-pairs x 4 e per thread
__device__ __forceinline__ void red_store(ull* __restrict__ red, int qbase,
                                          int wp4, int scol, ull a[4][4])
{
#pragma unroll
    for (int jj = 0; jj < 4; ++jj) {
        ull* rp = red + qbase + (wp4 + jj) * RED_ROW;
        *reinterpret_cast<ulonglong2*>(rp + scol) =
            make_ulonglong2(a[jj][0], a[jj][1]);
        *reinterpret_cast<ulonglong2*>(rp + 16 + scol) =
            make_ulonglong2(a[jj][2], a[jj][3]);
    }
}

__global__ void __launch_bounds__(NTHREADS, 1)
rnn_fused_kernel(const float* __restrict__ x,
                 const float* __restrict__ Wih0, const float* __restrict__ Whh0,
                 const float* __restrict__ bih0, const float* __restrict__ bhh0,
                 const float* __restrict__ Wih1, const float* __restrict__ Whh1,
                 const float* __restrict__ bih1, const float* __restrict__ bhh1,
                 const float* __restrict__ Wih2, const float* __restrict__ Whh2,
                 const float* __restrict__ bih2, const float* __restrict__ bhh2,
                 const float* __restrict__ fc1w, const float* __restrict__ fc1b,
                 const float* __restrict__ fc2w, const float* __restrict__ fc2b,
                 float* __restrict__ out)
{
    extern __shared__ ull smu[];
    float* smf = (float*)smu;
    const int tid = threadIdx.x;

    // ---- zero all smem ----
    {
        uint4* p4 = reinterpret_cast<uint4*>(smu);
        for (int i = tid; i < (int)(U_END / 2); i += NTHREADS)
            p4[i] = make_uint4(0, 0, 0, 0);
    }
    __syncthreads();

    // ---- stage weights [k][j] ----
    for (int idx = tid; idx < 64 * F_IN; idx += NTHREADS) {
        int j = idx / F_IN, f = idx - j * F_IN;
        smf[WF_A + f * WROW + j] = Wih0[idx];
    }
    for (int idx = tid; idx < 64 * 64; idx += NTHREADS) {
        int j = idx >> 6, k = idx & 63;
        smf[WF_A + (16 + k) * WROW + j] = Whh0[idx];
        smf[WF_B + k * WROW + j]        = Wih1[idx];
        smf[WF_B + (64 + k) * WROW + j] = Whh1[idx];
        smf[WF_C + k * WROW + j]        = Wih2[idx];
        smf[WF_C + (64 + k) * WROW + j] = Whh2[idx];
    }

    // ---- producer mapping: 8 warps = j-octet; lane = kc(4) x u(8) ----
    const int w    = tid >> 5;
    const int lane = tid & 31;
    const int kc   = lane >> 3;
    const int u    = lane & 7;
    const int w8   = w * 8;
    const int wp4  = w * 4;
    const int u4   = u * 4;
    const int scol = 2 * u;

    // ---- finisher mapping ----
    const int fjp = tid >> 3;
    const int fu  = tid & 7;
    const int fcol = 2 * fu;
    const int fj0 = 2 * fjp;

    const ull bf0 = pack2(bih0[fj0] + bhh0[fj0], bih0[fj0+1] + bhh0[fj0+1]);
    const ull bf1 = pack2(bih1[fj0] + bhh1[fj0], bih1[fj0+1] + bhh1[fj0+1]);
    const ull bf2 = pack2(bih2[fj0] + bhh2[fj0], bih2[fj0+1] + bhh2[fj0+1]);

    const float* xblk = x + (size_t)blockIdx.x * ELEMS * T_STEPS * F_IN;
    float* xs_f = (float*)(smu + U_XS);
    ull* red = smu + U_RED;
    float* H0f = (float*)(smu + U_H0);
    float* H1f = (float*)(smu + U_H1);
    float* H2f = (float*)(smu + U_H2);

    const int xe0 = tid / F_IN,  xf0 = tid - xe0 * F_IN;
    const int xi1 = tid + NTHREADS;
    const int xe1 = xi1 / F_IN,  xf1 = xi1 - xe1 * F_IN;
    const bool xa1 = (xi1 < ELEMS * F_IN);

    xs_f[xf0 * 36 + xe0] = xblk[xe0 * (T_STEPS * F_IN) + xf0];
    if (xa1) xs_f[xf1 * 36 + xe1] = xblk[xe1 * (T_STEPS * F_IN) + xf1];
    __syncthreads();

    for (int s = 0; s < NSUPER; ++s) {
        float xp0 = 0.0f, xp1 = 0.0f;
        const bool xstage = (s <= T_STEPS - 2);
        if (xstage) {
            xp0 = xblk[xe0 * (T_STEPS * F_IN) + (s + 1) * F_IN + xf0];
            if (xa1) xp1 = xblk[xe1 * (T_STEPS * F_IN) + (s + 1) * F_IN + xf1];
        }

        // ============ MV phase: 3 jobs INTERLEAVED (3 indep chains) =======
        {
            ull aA[4][4] = {}, aB[4][4] = {}, aC[4][4] = {};
#pragma unroll 4
            for (int i = 0; i < 20; ++i) {
                int k = kc + 4 * i;
                mv_one(smf + WF_A, xs_f, k, w8, u4, aA);
                mv_one(smf + WF_B, H0f, k, w8, u4, aB);
                mv_one(smf + WF_C, H1f, k, w8, u4, aC);
            }
#pragma unroll 4
            for (int i = 20; i < 32; ++i) {
                int k = kc + 4 * i;
                mv_one(smf + WF_B, H0f, k, w8, u4, aB);
                mv_one(smf + WF_C, H1f, k, w8, u4, aC);
            }
            red_store(red, (0 * 4 + kc) * RED_Q, wp4, scol, aA);
            red_store(red, (1 * 4 + kc) * RED_Q, wp4, scol, aB);
            red_store(red, (2 * 4 + kc) * RED_Q, wp4, scol, aC);
        }
        __syncthreads();

        // ============ FINISH phase ============
#pragma unroll
        for (int L = 0; L < 3; ++L) {
            bool valid = (L == 0) ? (s <= T_STEPS - 1)
                       : (L == 1) ? (s >= 1 && s <= T_STEPS)
                                  : (s >= 2);
            if (!valid) continue;
            ull s0 = 0, s1 = 0, s2 = 0, s3 = 0;
#pragma unroll
            for (int q = 0; q < 4; ++q) {
                const ull* rp = red + (L * 4 + q) * RED_Q + fjp * RED_ROW;
                ulonglong2 va = *reinterpret_cast<const ulonglong2*>(rp + fcol);
                ulonglong2 vb = *reinterpret_cast<const ulonglong2*>(rp + 16 + fcol);
                s0 = add2(s0, va.x); s1 = add2(s1, va.y);
                s2 = add2(s2, vb.x); s3 = add2(s3, vb.y);
            }
            ull bp = (L == 0) ? bf0 : (L == 1) ? bf1 : bf2;
            float* Hf = (L == 0) ? H0f : (L == 1) ? H1f : H2f;
            ull r0 = tanh2(add2(s0, bp));
            ull r1 = tanh2(add2(s1, bp));
            ull r2 = tanh2(add2(s2, bp));
            ull r3 = tanh2(add2(s3, bp));
            float lo, hi;
            int e0 = 4 * fu;
            unpack2(r0, lo, hi);
            Hf[fj0 * 36 + e0]     = lo; Hf[(fj0 + 1) * 36 + e0]     = hi;
            unpack2(r1, lo, hi);
            Hf[fj0 * 36 + e0 + 1] = lo; Hf[(fj0 + 1) * 36 + e0 + 1] = hi;
            unpack2(r2, lo, hi);
            Hf[fj0 * 36 + e0 + 2] = lo; Hf[(fj0 + 1) * 36 + e0 + 2] = hi;
            unpack2(r3, lo, hi);
            Hf[fj0 * 36 + e0 + 3] = lo; Hf[(fj0 + 1) * 36 + e0 + 3] = hi;
        }
        if (xstage) {
            xs_f[xf0 * 36 + xe0] = xp0;
            if (xa1) xs_f[xf1 * 36 + xe1] = xp1;
        }
        __syncthreads();
    }

    // ---- FC head on final h2 (H2 rows stride 36 f32) ----
    {
        int e  = tid >> 3;
        int mg = tid & 7;
        float contrib = 0.0f;
#pragma unroll
        for (int mi = 0; mi < 4; ++mi) {
            int m = mg * 4 + mi;
            float sfc = fc1b[m];
#pragma unroll 16
            for (int k = 0; k < HID; ++k)
                sfc = fmaf(fc1w[m * HID + k], H2f[k * 36 + e], sfc);
            contrib = fmaf(fc2w[m], fmaxf(sfc, 0.0f), contrib);
        }
        __syncthreads();
        float* fred = (float*)(smu + U_FCRED);
        fred[tid] = contrib;
    }
    __syncthreads();
    if (tid < ELEMS) {
        float* fred = (float*)(smu + U_FCRED);
        float sfc = fc2b[0];
#pragma unroll
        for (int i = 0; i < 8; ++i) sfc += fred[tid * 8 + i];
        out[blockIdx.x * ELEMS + tid] = sfc;
    }
}

extern "C" void kernel_launch(void* const* d_in, const int* in_sizes, int n_in,
                              void* d_out, int out_size)
{
    const float* x    = (const float*)d_in[0];
    const float* Wih0 = (const float*)d_in[1];
    const float* Whh0 = (const float*)d_in[2];
    const float* bih0 = (const float*)d_in[3];
    const float* bhh0 = (const float*)d_in[4];
    const float* Wih1 = (const float*)d_in[5];
    const float* Whh1 = (const float*)d_in[6];
    const float* bih1 = (const float*)d_in[7];
    const float* bhh1 = (const float*)d_in[8];
    const float* Wih2 = (const float*)d_in[9];
    const float* Whh2 = (const float*)d_in[10];
    const float* bih2 = (const float*)d_in[11];
    const float* bhh2 = (const float*)d_in[12];
    const float* fc1w = (const float*)d_in[13];
    const float* fc1b = (const float*)d_in[14];
    const float* fc2w = (const float*)d_in[15];
    const float* fc2b = (const float*)d_in[16];
    float* out = (float*)d_out;

    cudaFuncSetAttribute(rnn_fused_kernel,
                         cudaFuncAttributeMaxDynamicSharedMemorySize, SMEM_BYTES);

    rnn_fused_kernel<<<NBLOCKS, NTHREADS, SMEM_BYTES>>>(
        x, Wih0, Whh0, bih0, bhh0,
        Wih1, Whh1, bih1, bhh1,
        Wih2, Whh2, bih2, bhh2,
        fc1w, fc1b, fc2w, fc2b, out);
}

// round 15
// speedup vs baseline: 1.0036x; 1.0036x over previous
#include <cuda_runtime.h>

// ---------------------------------------------------------------------------
// RNN_32109175505717: 3-layer tanh RNN (B=4096, T=128, HID=64, F=14) + FC head
// R15 = R13 (256 thr, layer-skew pipeline, j-pair accumulators, ksplit 4,
// 2 barriers/step) + two bounded edits:
//   1. jobs B & C interleaved (2 chains, 32 accs — R14's 3-chain/48-acc
//      version blew regs to 184 and regressed; this is the controlled retry)
//   2. finish H-stores transposed: 2x STS.128 per job instead of 8x STS.32
// ---------------------------------------------------------------------------

#define HID      64
#define F_IN     14
#define T_STEPS  128
#define ELEMS    32
#define NTHREADS 256
#define NBLOCKS  128
#define NSUPER   (T_STEPS + 2)

typedef unsigned long long ull;

// ---- float-region (weights [k][j], 68-float rows) -------------------------
#define WROW   68
#define WF_A   0                       // 80 rows: [Wih0(14); zero(2); Whh0(64)]
#define WF_B   (WF_A + 80*WROW)        // 128 rows: [Wih1; Whh1]
#define WF_C   (WF_B + 128*WROW)       // 128 rows: [Wih2; Whh2]
#define WF_END (WF_C + 128*WROW)       // 22848 floats
// ---- ull-region -----------------------------------------------------------
#define U_XS   (WF_END/2)
#define U_H0   (U_XS + 16*18)
#define U_H1   (U_H0 + 64*18)
#define U_H2   (U_H1 + 64*18)
#define U_RED  (U_H2 + 64*18)          // 12 quadrants x [32 jp][36 ull]
#define RED_Q  1152
#define RED_ROW 36
#define U_END  (U_RED + 12*RED_Q)      // 231936 B
#define U_FCRED U_RED
#define SMEM_BYTES (U_END * 8)

// ---- f32x2 helpers --------------------------------------------------------
__device__ __forceinline__ ull pack2(float lo, float hi) {
    ull r; asm("mov.b64 %0, {%1, %2};" : "=l"(r) : "f"(lo), "f"(hi)); return r;
}
__device__ __forceinline__ void unpack2(ull v, float& lo, float& hi) {
    asm("mov.b64 {%0, %1}, %2;" : "=f"(lo), "=f"(hi) : "l"(v));
}
__device__ __forceinline__ ull fma2(ull a, ull b, ull c) {
    ull d; asm("fma.rn.f32x2 %0, %1, %2, %3;" : "=l"(d) : "l"(a), "l"(b), "l"(c));
    return d;
}
__device__ __forceinline__ ull add2(ull a, ull b) {
    ull d; asm("add.rn.f32x2 %0, %1, %2;" : "=l"(d) : "l"(a), "l"(b));
    return d;
}
__device__ __forceinline__ float fast_tanh(float x) {
    x = fminf(fmaxf(x, -12.0f), 12.0f);
    float e = __expf(x + x);
    return __fdividef(e - 1.0f, e + 1.0f);
}
__device__ __forceinline__ ull tanh2(ull v) {
    float a, b; unpack2(v, a, b);
    return pack2(fast_tanh(a), fast_tanh(b));
}

// ---- one k-row: 4 j-pairs x 4 e ------------------------------------------
__device__ __forceinline__ void mv_one(const float* __restrict__ wf,
                                       const float* __restrict__ hb,
                                       int k, int w8, int u4, ull a[4][4])
{
    float4 hv = *reinterpret_cast<const float4*>(hb + k * 36 + u4);
    const float* wr = wf + k * WROW + w8;
    ulonglong2 w01 = *reinterpret_cast<const ulonglong2*>(wr);
    ulonglong2 w23 = *reinterpret_cast<const ulonglong2*>(wr + 4);
    ull ph;
    ph = pack2(hv.x, hv.x);
    a[0][0]=fma2(w01.x,ph,a[0][0]); a[1][0]=fma2(w01.y,ph,a[1][0]);
    a[2][0]=fma2(w23.x,ph,a[2][0]); a[3][0]=fma2(w23.y,ph,a[3][0]);
    ph = pack2(hv.y, hv.y);
    a[0][1]=fma2(w01.x,ph,a[0][1]); a[1][1]=fma2(w01.y,ph,a[1][1]);
    a[2][1]=fma2(w23.x,ph,a[2][1]); a[3][1]=fma2(w23.y,ph,a[3][1]);
    ph = pack2(hv.z, hv.z);
    a[0][2]=fma2(w01.x,ph,a[0][2]); a[1][2]=fma2(w01.y,ph,a[1][2]);
    a[2][2]=fma2(w23.x,ph,a[2][2]); a[3][2]=fma2(w23.y,ph,a[3][2]);
    ph = pack2(hv.w, hv.w);
    a[0][3]=fma2(w01.x,ph,a[0][3]); a[1][3]=fma2(w01.y,ph,a[1][3]);
    a[2][3]=fma2(w23.x,ph,a[2][3]); a[3][3]=fma2(w23.y,ph,a[3][3]);
}

__device__ __forceinline__ void red_store(ull* __restrict__ red, int qbase,
                                          int wp4, int scol, ull a[4][4])
{
#pragma unroll
    for (int jj = 0; jj < 4; ++jj) {
        ull* rp = red + qbase + (wp4 + jj) * RED_ROW;
        *reinterpret_cast<ulonglong2*>(rp + scol) =
            make_ulonglong2(a[jj][0], a[jj][1]);
        *reinterpret_cast<ulonglong2*>(rp + 16 + scol) =
            make_ulonglong2(a[jj][2], a[jj][3]);
    }
}

__global__ void __launch_bounds__(NTHREADS, 1)
rnn_fused_kernel(const float* __restrict__ x,
                 const float* __restrict__ Wih0, const float* __restrict__ Whh0,
                 const float* __restrict__ bih0, const float* __restrict__ bhh0,
                 const float* __restrict__ Wih1, const float* __restrict__ Whh1,
                 const float* __restrict__ bih1, const float* __restrict__ bhh1,
                 const float* __restrict__ Wih2, const float* __restrict__ Whh2,
                 const float* __restrict__ bih2, const float* __restrict__ bhh2,
                 const float* __restrict__ fc1w, const float* __restrict__ fc1b,
                 const float* __restrict__ fc2w, const float* __restrict__ fc2b,
                 float* __restrict__ out)
{
    extern __shared__ ull smu[];
    float* smf = (float*)smu;
    const int tid = threadIdx.x;

    // ---- zero all smem ----
    {
        uint4* p4 = reinterpret_cast<uint4*>(smu);
        for (int i = tid; i < (int)(U_END / 2); i += NTHREADS)
            p4[i] = make_uint4(0, 0, 0, 0);
    }
    __syncthreads();

    // ---- stage weights [k][j] ----
    for (int idx = tid; idx < 64 * F_IN; idx += NTHREADS) {
        int j = idx / F_IN, f = idx - j * F_IN;
        smf[WF_A + f * WROW + j] = Wih0[idx];
    }
    for (int idx = tid; idx < 64 * 64; idx += NTHREADS) {
        int j = idx >> 6, k = idx & 63;
        smf[WF_A + (16 + k) * WROW + j] = Whh0[idx];
        smf[WF_B + k * WROW + j]        = Wih1[idx];
        smf[WF_B + (64 + k) * WROW + j] = Whh1[idx];
        smf[WF_C + k * WROW + j]        = Wih2[idx];
        smf[WF_C + (64 + k) * WROW + j] = Whh2[idx];
    }

    // ---- producer mapping ----
    const int w    = tid >> 5;
    const int lane = tid & 31;
    const int kc   = lane >> 3;
    const int u    = lane & 7;
    const int w8   = w * 8;
    const int wp4  = w * 4;
    const int u4   = u * 4;
    const int scol = 2 * u;

    // ---- finisher mapping ----
    const int fjp = tid >> 3;
    const int fu  = tid & 7;
    const int fcol = 2 * fu;
    const int fj0 = 2 * fjp;

    const ull bf0 = pack2(bih0[fj0] + bhh0[fj0], bih0[fj0+1] + bhh0[fj0+1]);
    const ull bf1 = pack2(bih1[fj0] + bhh1[fj0], bih1[fj0+1] + bhh1[fj0+1]);
    const ull bf2 = pack2(bih2[fj0] + bhh2[fj0], bih2[fj0+1] + bhh2[fj0+1]);

    const float* xblk = x + (size_t)blockIdx.x * ELEMS * T_STEPS * F_IN;
    float* xs_f = (float*)(smu + U_XS);
    ull* red = smu + U_RED;
    float* H0f = (float*)(smu + U_H0);
    float* H1f = (float*)(smu + U_H1);
    float* H2f = (float*)(smu + U_H2);

    const int xe0 = tid / F_IN,  xf0 = tid - xe0 * F_IN;
    const int xi1 = tid + NTHREADS;
    const int xe1 = xi1 / F_IN,  xf1 = xi1 - xe1 * F_IN;
    const bool xa1 = (xi1 < ELEMS * F_IN);

    xs_f[xf0 * 36 + xe0] = xblk[xe0 * (T_STEPS * F_IN) + xf0];
    if (xa1) xs_f[xf1 * 36 + xe1] = xblk[xe1 * (T_STEPS * F_IN) + xf1];
    __syncthreads();

    for (int s = 0; s < NSUPER; ++s) {
        float xp0 = 0.0f, xp1 = 0.0f;
        const bool xstage = (s <= T_STEPS - 2);
        if (xstage) {
            xp0 = xblk[xe0 * (T_STEPS * F_IN) + (s + 1) * F_IN + xf0];
            if (xa1) xp1 = xblk[xe1 * (T_STEPS * F_IN) + (s + 1) * F_IN + xf1];
        }

        // ============ MV phase ============
        {   // job A alone (20 iters)
            ull aA[4][4] = {};
#pragma unroll 5
            for (int i = 0; i < 20; ++i)
                mv_one(smf + WF_A, xs_f, kc + 4 * i, w8, u4, aA);
            red_store(red, (0 * 4 + kc) * RED_Q, wp4, scol, aA);
        }
        {   // jobs B & C interleaved: 2 independent chains, 32 accs
            ull aB[4][4] = {}, aC[4][4] = {};
#pragma unroll 4
            for (int i = 0; i < 32; ++i) {
                int k = kc + 4 * i;
                mv_one(smf + WF_B, H0f, k, w8, u4, aB);
                mv_one(smf + WF_C, H1f, k, w8, u4, aC);
            }
            red_store(red, (1 * 4 + kc) * RED_Q, wp4, scol, aB);
            red_store(red, (2 * 4 + kc) * RED_Q, wp4, scol, aC);
        }
        __syncthreads();

        // ============ FINISH phase ============
#pragma unroll
        for (int L = 0; L < 3; ++L) {
            bool valid = (L == 0) ? (s <= T_STEPS - 1)
                       : (L == 1) ? (s >= 1 && s <= T_STEPS)
                                  : (s >= 2);
            if (!valid) continue;
            ull s0 = 0, s1 = 0, s2 = 0, s3 = 0;
#pragma unroll
            for (int q = 0; q < 4; ++q) {
                const ull* rp = red + (L * 4 + q) * RED_Q + fjp * RED_ROW;
                ulonglong2 va = *reinterpret_cast<const ulonglong2*>(rp + fcol);
                ulonglong2 vb = *reinterpret_cast<const ulonglong2*>(rp + 16 + fcol);
                s0 = add2(s0, va.x); s1 = add2(s1, va.y);
                s2 = add2(s2, vb.x); s3 = add2(s3, vb.y);
            }
            ull bp = (L == 0) ? bf0 : (L == 1) ? bf1 : bf2;
            float* Hf = (L == 0) ? H0f : (L == 1) ? H1f : H2f;
            ull r0 = tanh2(add2(s0, bp));
            ull r1 = tanh2(add2(s1, bp));
            ull r2 = tanh2(add2(s2, bp));
            ull r3 = tanh2(add2(s3, bp));
            // transpose to per-row float4s: 2x STS.128 instead of 8x STS.32
            float l0, h0v, l1, h1v, l2, h2v, l3, h3v;
            unpack2(r0, l0, h0v); unpack2(r1, l1, h1v);
            unpack2(r2, l2, h2v); unpack2(r3, l3, h3v);
            int e0 = 4 * fu;
            *reinterpret_cast<float4*>(Hf + fj0 * 36 + e0) =
                make_float4(l0, l1, l2, l3);
            *reinterpret_cast<float4*>(Hf + (fj0 + 1) * 36 + e0) =
                make_float4(h0v, h1v, h2v, h3v);
        }
        if (xstage) {
            xs_f[xf0 * 36 + xe0] = xp0;
            if (xa1) xs_f[xf1 * 36 + xe1] = xp1;
        }
        __syncthreads();
    }

    // ---- FC head on final h2 (H2 rows stride 36 f32) ----
    {
        int e  = tid >> 3;
        int mg = tid & 7;
        float contrib = 0.0f;
#pragma unroll
        for (int mi = 0; mi < 4; ++mi) {
            int m = mg * 4 + mi;
            float sfc = fc1b[m];
#pragma unroll 16
            for (int k = 0; k < HID; ++k)
                sfc = fmaf(fc1w[m * HID + k], H2f[k * 36 + e], sfc);
            contrib = fmaf(fc2w[m], fmaxf(sfc, 0.0f), contrib);
        }
        __syncthreads();
        float* fred = (float*)(smu + U_FCRED);
        fred[tid] = contrib;
    }
    __syncthreads();
    if (tid < ELEMS) {
        float* fred = (float*)(smu + U_FCRED);
        float sfc = fc2b[0];
#pragma unroll
        for (int i = 0; i < 8; ++i) sfc += fred[tid * 8 + i];
        out[blockIdx.x * ELEMS + tid] = sfc;
    }
}

extern "C" void kernel_launch(void* const* d_in, const int* in_sizes, int n_in,
                              void* d_out, int out_size)
{
    const float* x    = (const float*)d_in[0];
    const float* Wih0 = (const float*)d_in[1];
    const float* Whh0 = (const float*)d_in[2];
    const float* bih0 = (const float*)d_in[3];
    const float* bhh0 = (const float*)d_in[4];
    const float* Wih1 = (const float*)d_in[5];
    const float* Whh1 = (const float*)d_in[6];
    const float* bih1 = (const float*)d_in[7];
    const float* bhh1 = (const float*)d_in[8];
    const float* Wih2 = (const float*)d_in[9];
    const float* Whh2 = (const float*)d_in[10];
    const float* bih2 = (const float*)d_in[11];
    const float* bhh2 = (const float*)d_in[12];
    const float* fc1w = (const float*)d_in[13];
    const float* fc1b = (const float*)d_in[14];
    const float* fc2w = (const float*)d_in[15];
    const float* fc2b = (const float*)d_in[16];
    float* out = (float*)d_out;

    cudaFuncSetAttribute(rnn_fused_kernel,
                         cudaFuncAttributeMaxDynamicSharedMemorySize, SMEM_BYTES);

    rnn_fused_kernel<<<NBLOCKS, NTHREADS, SMEM_BYTES>>>(
        x, Wih0, Whh0, bih0, bhh0,
        Wih1, Whh1, bih1, bhh1,
        Wih2, Whh2, bih2, bhh2,
        fc1w, fc1b, fc2w, fc2b, out);
}

// round 16
// speedup vs baseline: 1.0452x; 1.0415x over previous
#include <cuda_runtime.h>

// ---------------------------------------------------------------------------
// RNN_32109175505717: 3-layer tanh RNN (B=4096, T=128, HID=64, F=14) + FC head
// R16 = R13 exactly (best: 594.8us; 256 thr, layer-skew pipeline, j-pair
// accumulators, ksplit 4, sequential jobs, 2 barriers/step) + ONE isolated
// edit: finish-phase H-stores transposed to 2x STS.128 per job instead of
// 8x STS.32 (-54 LSU issues/thread/step). R14/R15 proved manual interleaving
// only burns registers; this keeps R13's scheduling untouched.
// ---------------------------------------------------------------------------

#define HID      64
#define F_IN     14
#define T_STEPS  128
#define ELEMS    32
#define NTHREADS 256
#define NBLOCKS  128
#define NSUPER   (T_STEPS + 2)

typedef unsigned long long ull;

// ---- float-region (weights [k][j], 68-float rows) -------------------------
#define WROW   68
#define WF_A   0                       // 80 rows: [Wih0(14); zero(2); Whh0(64)]
#define WF_B   (WF_A + 80*WROW)        // 128 rows: [Wih1; Whh1]
#define WF_C   (WF_B + 128*WROW)       // 128 rows: [Wih2; Whh2]
#define WF_END (WF_C + 128*WROW)       // 22848 floats
// ---- ull-region -----------------------------------------------------------
#define U_XS   (WF_END/2)
#define U_H0   (U_XS + 16*18)
#define U_H1   (U_H0 + 64*18)
#define U_H2   (U_H1 + 64*18)
#define U_RED  (U_H2 + 64*18)          // 12 quadrants x [32 jp][36 ull]
#define RED_Q  1152
#define RED_ROW 36
#define U_END  (U_RED + 12*RED_Q)      // 231936 B
#define U_FCRED U_RED
#define SMEM_BYTES (U_END * 8)

// ---- f32x2 helpers --------------------------------------------------------
__device__ __forceinline__ ull pack2(float lo, float hi) {
    ull r; asm("mov.b64 %0, {%1, %2};" : "=l"(r) : "f"(lo), "f"(hi)); return r;
}
__device__ __forceinline__ void unpack2(ull v, float& lo, float& hi) {
    asm("mov.b64 {%0, %1}, %2;" : "=f"(lo), "=f"(hi) : "l"(v));
}
__device__ __forceinline__ ull fma2(ull a, ull b, ull c) {
    ull d; asm("fma.rn.f32x2 %0, %1, %2, %3;" : "=l"(d) : "l"(a), "l"(b), "l"(c));
    return d;
}
__device__ __forceinline__ ull add2(ull a, ull b) {
    ull d; asm("add.rn.f32x2 %0, %1, %2;" : "=l"(d) : "l"(a), "l"(b));
    return d;
}
__device__ __forceinline__ float fast_tanh(float x) {
    x = fminf(fmaxf(x, -12.0f), 12.0f);
    float e = __expf(x + x);
    return __fdividef(e - 1.0f, e + 1.0f);
}
__device__ __forceinline__ ull tanh2(ull v) {
    float a, b; unpack2(v, a, b);
    return pack2(fast_tanh(a), fast_tanh(b));
}

// ---- one k-row: 4 j-pairs x 4 e ------------------------------------------
__device__ __forceinline__ void mv_one(const float* __restrict__ wf,
                                       const float* __restrict__ hb,
                                       int k, int w8, int u4, ull a[4][4])
{
    float4 hv = *reinterpret_cast<const float4*>(hb + k * 36 + u4);
    const float* wr = wf + k * WROW + w8;
    ulonglong2 w01 = *reinterpret_cast<const ulonglong2*>(wr);
    ulonglong2 w23 = *reinterpret_cast<const ulonglong2*>(wr + 4);
    ull ph;
    ph = pack2(hv.x, hv.x);
    a[0][0]=fma2(w01.x,ph,a[0][0]); a[1][0]=fma2(w01.y,ph,a[1][0]);
    a[2][0]=fma2(w23.x,ph,a[2][0]); a[3][0]=fma2(w23.y,ph,a[3][0]);
    ph = pack2(hv.y, hv.y);
    a[0][1]=fma2(w01.x,ph,a[0][1]); a[1][1]=fma2(w01.y,ph,a[1][1]);
    a[2][1]=fma2(w23.x,ph,a[2][1]); a[3][1]=fma2(w23.y,ph,a[3][1]);
    ph = pack2(hv.z, hv.z);
    a[0][2]=fma2(w01.x,ph,a[0][2]); a[1][2]=fma2(w01.y,ph,a[1][2]);
    a[2][2]=fma2(w23.x,ph,a[2][2]); a[3][2]=fma2(w23.y,ph,a[3][2]);
    ph = pack2(hv.w, hv.w);
    a[0][3]=fma2(w01.x,ph,a[0][3]); a[1][3]=fma2(w01.y,ph,a[1][3]);
    a[2][3]=fma2(w23.x,ph,a[2][3]); a[3][3]=fma2(w23.y,ph,a[3][3]);
}

__device__ __forceinline__ void red_store(ull* __restrict__ red, int qbase,
                                          int wp4, int scol, ull a[4][4])
{
#pragma unroll
    for (int jj = 0; jj < 4; ++jj) {
        ull* rp = red + qbase + (wp4 + jj) * RED_ROW;
        *reinterpret_cast<ulonglong2*>(rp + scol) =
            make_ulonglong2(a[jj][0], a[jj][1]);
        *reinterpret_cast<ulonglong2*>(rp + 16 + scol) =
            make_ulonglong2(a[jj][2], a[jj][3]);
    }
}

__global__ void __launch_bounds__(NTHREADS, 1)
rnn_fused_kernel(const float* __restrict__ x,
                 const float* __restrict__ Wih0, const float* __restrict__ Whh0,
                 const float* __restrict__ bih0, const float* __restrict__ bhh0,
                 const float* __restrict__ Wih1, const float* __restrict__ Whh1,
                 const float* __restrict__ bih1, const float* __restrict__ bhh1,
                 const float* __restrict__ Wih2, const float* __restrict__ Whh2,
                 const float* __restrict__ bih2, const float* __restrict__ bhh2,
                 const float* __restrict__ fc1w, const float* __restrict__ fc1b,
                 const float* __restrict__ fc2w, const float* __restrict__ fc2b,
                 float* __restrict__ out)
{
    extern __shared__ ull smu[];
    float* smf = (float*)smu;
    const int tid = threadIdx.x;

    // ---- zero all smem ----
    {
        uint4* p4 = reinterpret_cast<uint4*>(smu);
        for (int i = tid; i < (int)(U_END / 2); i += NTHREADS)
            p4[i] = make_uint4(0, 0, 0, 0);
    }
    __syncthreads();

    // ---- stage weights [k][j] ----
    for (int idx = tid; idx < 64 * F_IN; idx += NTHREADS) {
        int j = idx / F_IN, f = idx - j * F_IN;
        smf[WF_A + f * WROW + j] = Wih0[idx];
    }
    for (int idx = tid; idx < 64 * 64; idx += NTHREADS) {
        int j = idx >> 6, k = idx & 63;
        smf[WF_A + (16 + k) * WROW + j] = Whh0[idx];
        smf[WF_B + k * WROW + j]        = Wih1[idx];
        smf[WF_B + (64 + k) * WROW + j] = Whh1[idx];
        smf[WF_C + k * WROW + j]        = Wih2[idx];
        smf[WF_C + (64 + k) * WROW + j] = Whh2[idx];
    }

    // ---- producer mapping: 8 warps = j-octet; lane = kc(4) x u(8) ----
    const int w    = tid >> 5;
    const int lane = tid & 31;
    const int kc   = lane >> 3;
    const int u    = lane & 7;
    const int w8   = w * 8;
    const int wp4  = w * 4;
    const int u4   = u * 4;
    const int scol = 2 * u;

    // ---- finisher mapping ----
    const int fjp = tid >> 3;
    const int fu  = tid & 7;
    const int fcol = 2 * fu;
    const int fj0 = 2 * fjp;

    const ull bf0 = pack2(bih0[fj0] + bhh0[fj0], bih0[fj0+1] + bhh0[fj0+1]);
    const ull bf1 = pack2(bih1[fj0] + bhh1[fj0], bih1[fj0+1] + bhh1[fj0+1]);
    const ull bf2 = pack2(bih2[fj0] + bhh2[fj0], bih2[fj0+1] + bhh2[fj0+1]);

    const float* xblk = x + (size_t)blockIdx.x * ELEMS * T_STEPS * F_IN;
    float* xs_f = (float*)(smu + U_XS);
    ull* red = smu + U_RED;
    float* H0f = (float*)(smu + U_H0);
    float* H1f = (float*)(smu + U_H1);
    float* H2f = (float*)(smu + U_H2);

    const int xe0 = tid / F_IN,  xf0 = tid - xe0 * F_IN;
    const int xi1 = tid + NTHREADS;
    const int xe1 = xi1 / F_IN,  xf1 = xi1 - xe1 * F_IN;
    const bool xa1 = (xi1 < ELEMS * F_IN);

    xs_f[xf0 * 36 + xe0] = xblk[xe0 * (T_STEPS * F_IN) + xf0];
    if (xa1) xs_f[xf1 * 36 + xe1] = xblk[xe1 * (T_STEPS * F_IN) + xf1];
    __syncthreads();

    for (int s = 0; s < NSUPER; ++s) {
        float xp0 = 0.0f, xp1 = 0.0f;
        const bool xstage = (s <= T_STEPS - 2);
        if (xstage) {
            xp0 = xblk[xe0 * (T_STEPS * F_IN) + (s + 1) * F_IN + xf0];
            if (xa1) xp1 = xblk[xe1 * (T_STEPS * F_IN) + (s + 1) * F_IN + xf1];
        }

        // ============ MV phase: 3 jobs SEQUENTIAL (R13 structure) =========
        {   // job A: L0(t=s) over [xs(16); H0] x W_A (80 rows)
            ull a[4][4] = {};
#pragma unroll 5
            for (int i = 0; i < 20; ++i)
                mv_one(smf + WF_A, xs_f, kc + 4 * i, w8, u4, a);
            red_store(red, (0 * 4 + kc) * RED_Q, wp4, scol, a);
        }
        {   // job B: L1(t=s-1) over [H0; H1] x W_B (128 rows)
            ull a[4][4] = {};
#pragma unroll 8
            for (int i = 0; i < 32; ++i)
                mv_one(smf + WF_B, H0f, kc + 4 * i, w8, u4, a);
            red_store(red, (1 * 4 + kc) * RED_Q, wp4, scol, a);
        }
        {   // job C: L2(t=s-2) over [H1; H2] x W_C (128 rows)
            ull a[4][4] = {};
#pragma unroll 8
            for (int i = 0; i < 32; ++i)
                mv_one(smf + WF_C, H1f, kc + 4 * i, w8, u4, a);
            red_store(red, (2 * 4 + kc) * RED_Q, wp4, scol, a);
        }
        __syncthreads();

        // ============ FINISH phase (transposed STS.128 H-stores) ==========
#pragma unroll
        for (int L = 0; L < 3; ++L) {
            bool valid = (L == 0) ? (s <= T_STEPS - 1)
                       : (L == 1) ? (s >= 1 && s <= T_STEPS)
                                  : (s >= 2);
            if (!valid) continue;
            ull s0 = 0, s1 = 0, s2 = 0, s3 = 0;
#pragma unroll
            for (int q = 0; q < 4; ++q) {
                const ull* rp = red + (L * 4 + q) * RED_Q + fjp * RED_ROW;
                ulonglong2 va = *reinterpret_cast<const ulonglong2*>(rp + fcol);
                ulonglong2 vb = *reinterpret_cast<const ulonglong2*>(rp + 16 + fcol);
                s0 = add2(s0, va.x); s1 = add2(s1, va.y);
                s2 = add2(s2, vb.x); s3 = add2(s3, vb.y);
            }
            ull bp = (L == 0) ? bf0 : (L == 1) ? bf1 : bf2;
            float* Hf = (L == 0) ? H0f : (L == 1) ? H1f : H2f;
            ull r0 = tanh2(add2(s0, bp));
            ull r1 = tanh2(add2(s1, bp));
            ull r2 = tanh2(add2(s2, bp));
            ull r3 = tanh2(add2(s3, bp));
            float l0, h0v, l1, h1v, l2, h2v, l3, h3v;
            unpack2(r0, l0, h0v); unpack2(r1, l1, h1v);
            unpack2(r2, l2, h2v); unpack2(r3, l3, h3v);
            int e0 = 4 * fu;
            *reinterpret_cast<float4*>(Hf + fj0 * 36 + e0) =
                make_float4(l0, l1, l2, l3);
            *reinterpret_cast<float4*>(Hf + (fj0 + 1) * 36 + e0) =
                make_float4(h0v, h1v, h2v, h3v);
        }
        if (xstage) {
            xs_f[xf0 * 36 + xe0] = xp0;
            if (xa1) xs_f[xf1 * 36 + xe1] = xp1;
        }
        __syncthreads();
    }

    // ---- FC head on final h2 (H2 rows stride 36 f32) ----
    {
        int e  = tid >> 3;
        int mg = tid & 7;
        float contrib = 0.0f;
#pragma unroll
        for (int mi = 0; mi < 4; ++mi) {
            int m = mg * 4 + mi;
            float sfc = fc1b[m];
#pragma unroll 16
            for (int k = 0; k < HID; ++k)
                sfc = fmaf(fc1w[m * HID + k], H2f[k * 36 + e], sfc);
            contrib = fmaf(fc2w[m], fmaxf(sfc, 0.0f), contrib);
        }
        __syncthreads();
        float* fred = (float*)(smu + U_FCRED);
        fred[tid] = contrib;
    }
    __syncthreads();
    if (tid < ELEMS) {
        float* fred = (float*)(smu + U_FCRED);
        float sfc = fc2b[0];
#pragma unroll
        for (int i = 0; i < 8; ++i) sfc += fred[tid * 8 + i];
        out[blockIdx.x * ELEMS + tid] = sfc;
    }
}

extern "C" void kernel_launch(void* const* d_in, const int* in_sizes, int n_in,
                              void* d_out, int out_size)
{
    const float* x    = (const float*)d_in[0];
    const float* Wih0 = (const float*)d_in[1];
    const float* Whh0 = (const float*)d_in[2];
    const float* bih0 = (const float*)d_in[3];
    const float* bhh0 = (const float*)d_in[4];
    const float* Wih1 = (const float*)d_in[5];
    const float* Whh1 = (const float*)d_in[6];
    const float* bih1 = (const float*)d_in[7];
    const float* bhh1 = (const float*)d_in[8];
    const float* Wih2 = (const float*)d_in[9];
    const float* Whh2 = (const float*)d_in[10];
    const float* bih2 = (const float*)d_in[11];
    const float* bhh2 = (const float*)d_in[12];
    const float* fc1w = (const float*)d_in[13];
    const float* fc1b = (const float*)d_in[14];
    const float* fc2w = (const float*)d_in[15];
    const float* fc2b = (const float*)d_in[16];
    float* out = (float*)d_out;

    cudaFuncSetAttribute(rnn_fused_kernel,
                         cudaFuncAttributeMaxDynamicSharedMemorySize, SMEM_BYTES);

    rnn_fused_kernel<<<NBLOCKS, NTHREADS, SMEM_BYTES>>>(
        x, Wih0, Whh0, bih0, bhh0,
        Wih1, Whh1, bih1, bhh1,
        Wih2, Whh2, bih2, bhh2,
        fc1w, fc1b, fc2w, fc2b, out);
}